// round 1
// baseline (speedup 1.0000x reference)
#include <cuda_runtime.h>
#include <math.h>

#define SEQ   1024
#define DIM   1024
#define NHEAD 16
#define HDIM  64
#define BATCH 4
#define NTOK  (BATCH*SEQ)   // 4096

// Scratch (allocation-free rule: __device__ globals)
__device__ float g_q[BATCH*NHEAD*SEQ*HDIM];          // 16 MB  [B,H,S,Hd]
__device__ float g_k[BATCH*NHEAD*SEQ*HDIM];          // 16 MB
__device__ float g_v[BATCH*NHEAD*SEQ*HDIM];          // 16 MB
__device__ float g_scores[(long long)BATCH*NHEAD*SEQ*SEQ]; // 268 MB [B*H, S, S]
__device__ float g_wa[(long long)NTOK*DIM];          // 16 MB  [B,S,D]

// ---------------------------------------------------------------------------
// Tiled GEMM: C = alpha * A @ op(B) + bias
//   A: [M,K] row-major.
//   BMODE 0: B is [N,K] row-major (NT — dot of rows).
//   BMODE 1: B is [K,N] row-major (NN).
//   OUT_MODE 0: C[z*sC + m*N + n]
//   OUT_MODE 1: QKV scatter — m=(b,s), n=(h,d) -> [B,H,S,Hd]
//   OUT_MODE 2: wa scatter  — z=(b,h), out[((b*S+m)*DIM) + h*HDIM + n]
// Tile: BM=128, BN=64, BK=16, 256 threads, 8x4 per-thread microtile.
// ---------------------------------------------------------------------------
template<int BMODE, int OUT_MODE>
__global__ void __launch_bounds__(256, 2)
gemm_kernel(const float* __restrict__ A, const float* __restrict__ B,
            const float* __restrict__ bias, float* __restrict__ C,
            int M, int N, int K, float alpha,
            long long sA, long long sB, long long sC)
{
    __shared__ float As[16][128 + 4];
    __shared__ float Bs[16][64 + 4];

    const int tid  = threadIdx.x;
    const int tx   = tid & 15;        // 0..15 -> 4 output cols
    const int ty   = tid >> 4;        // 0..15 -> 8 output rows
    const int row0 = blockIdx.y * 128;
    const int col0 = blockIdx.x * 64;
    const int z    = blockIdx.z;

    const float* Ab = A + (long long)z * sA;
    const float* Bb = B + (long long)z * sB;

    float acc[8][4];
    #pragma unroll
    for (int i = 0; i < 8; i++)
        #pragma unroll
        for (int j = 0; j < 4; j++) acc[i][j] = 0.f;

    for (int k0 = 0; k0 < K; k0 += 16) {
        // ---- load A tile (transpose into As[k][m]), 2 float4 per thread ----
        #pragma unroll
        for (int r = 0; r < 2; r++) {
            int idx = tid + r * 256;              // 0..511
            int m   = idx >> 2;                   // 0..127
            int kq  = (idx & 3) << 2;             // 0,4,8,12
            float4 va = *(const float4*)(Ab + (long long)(row0 + m) * K + k0 + kq);
            As[kq + 0][m] = va.x;
            As[kq + 1][m] = va.y;
            As[kq + 2][m] = va.z;
            As[kq + 3][m] = va.w;
        }
        // ---- load B tile ----
        if (BMODE == 0) {                          // B [N,K]: transpose
            int n  = tid >> 2;                     // 0..63
            int kq = (tid & 3) << 2;               // 0,4,8,12
            float4 vb = *(const float4*)(Bb + (long long)(col0 + n) * K + k0 + kq);
            Bs[kq + 0][n] = vb.x;
            Bs[kq + 1][n] = vb.y;
            Bs[kq + 2][n] = vb.z;
            Bs[kq + 3][n] = vb.w;
        } else {                                   // B [K,N]: direct copy
            int k  = tid >> 4;                     // 0..15
            int nq = (tid & 15) << 2;              // 0..60
            float4 vb = *(const float4*)(Bb + (long long)(k0 + k) * N + col0 + nq);
            *(float4*)&Bs[k][nq] = vb;
        }
        __syncthreads();

        // ---- compute ----
        #pragma unroll
        for (int k = 0; k < 16; k++) {
            float4 a0 = *(const float4*)&As[k][ty * 8];
            float4 a1 = *(const float4*)&As[k][ty * 8 + 4];
            float4 b0 = *(const float4*)&Bs[k][tx * 4];
            float av[8] = {a0.x, a0.y, a0.z, a0.w, a1.x, a1.y, a1.z, a1.w};
            float bv[4] = {b0.x, b0.y, b0.z, b0.w};
            #pragma unroll
            for (int i = 0; i < 8; i++)
                #pragma unroll
                for (int j = 0; j < 4; j++)
                    acc[i][j] += av[i] * bv[j];
        }
        __syncthreads();
    }

    // ---- epilogue ----
    #pragma unroll
    for (int i = 0; i < 8; i++) {
        int gm = row0 + ty * 8 + i;
        #pragma unroll
        for (int j = 0; j < 4; j++) {
            int gn = col0 + tx * 4 + j;
            float v = acc[i][j] * alpha;
            if (bias) v += bias[gn];
            if (OUT_MODE == 0) {
                C[(long long)z * sC + (long long)gm * N + gn] = v;
            } else if (OUT_MODE == 1) {
                int b = gm >> 10, s = gm & 1023;
                int h = gn >> 6,  d = gn & 63;
                C[(((long long)(b * NHEAD + h) * SEQ + s) * HDIM) + d] = v;
            } else {
                int b = z >> 4, h = z & 15;
                C[(((long long)b * SEQ + gm) * DIM) + h * HDIM + gn] = v;
            }
        }
    }
}

// ---------------------------------------------------------------------------
// Row softmax in place. One block (256 threads) per row of 1024.
// ---------------------------------------------------------------------------
__global__ void __launch_bounds__(256)
softmax_kernel(float* __restrict__ scores)
{
    __shared__ float red[256];
    long long row = blockIdx.x;
    float* p = scores + row * SEQ;
    int tid = threadIdx.x;

    float4 x = ((float4*)p)[tid];
    float m = fmaxf(fmaxf(x.x, x.y), fmaxf(x.z, x.w));
    red[tid] = m; __syncthreads();
    #pragma unroll
    for (int s = 128; s > 0; s >>= 1) {
        if (tid < s) red[tid] = fmaxf(red[tid], red[tid + s]);
        __syncthreads();
    }
    float rowmax = red[0];
    __syncthreads();

    x.x = expf(x.x - rowmax);
    x.y = expf(x.y - rowmax);
    x.z = expf(x.z - rowmax);
    x.w = expf(x.w - rowmax);
    float sum = x.x + x.y + x.z + x.w;
    red[tid] = sum; __syncthreads();
    #pragma unroll
    for (int s = 128; s > 0; s >>= 1) {
        if (tid < s) red[tid] += red[tid + s];
        __syncthreads();
    }
    float inv = 1.f / red[0];
    x.x *= inv; x.y *= inv; x.z *= inv; x.w *= inv;
    ((float4*)p)[tid] = x;
}

// ---------------------------------------------------------------------------
extern "C" void kernel_launch(void* const* d_in, const int* in_sizes, int n_in,
                              void* d_out, int out_size)
{
    (void)in_sizes; (void)n_in; (void)out_size;
    const float* x  = (const float*)d_in[0];
    const float* Wq = (const float*)d_in[1];
    const float* bq = (const float*)d_in[2];
    const float* Wk = (const float*)d_in[3];
    const float* bk = (const float*)d_in[4];
    const float* Wv = (const float*)d_in[5];
    const float* bv = (const float*)d_in[6];
    const float* Wp = (const float*)d_in[7];
    const float* bp = (const float*)d_in[8];
    float* out = (float*)d_out;

    float *q, *k, *v, *sc, *wa;
    cudaGetSymbolAddress((void**)&q,  g_q);
    cudaGetSymbolAddress((void**)&k,  g_k);
    cudaGetSymbolAddress((void**)&v,  g_v);
    cudaGetSymbolAddress((void**)&sc, g_scores);
    cudaGetSymbolAddress((void**)&wa, g_wa);

    dim3 blk(256);

    // Q, K, V projections: [4096,1024] @ [1024,1024]^T + bias -> [B,H,S,Hd]
    dim3 gproj(DIM / 64, NTOK / 128, 1);
    gemm_kernel<0, 1><<<gproj, blk>>>(x, Wq, bq, q, NTOK, DIM, DIM, 1.f, 0, 0, 0);
    gemm_kernel<0, 1><<<gproj, blk>>>(x, Wk, bk, k, NTOK, DIM, DIM, 1.f, 0, 0, 0);
    gemm_kernel<0, 1><<<gproj, blk>>>(x, Wv, bv, v, NTOK, DIM, DIM, 1.f, 0, 0, 0);

    // scores = Q @ K^T / 8 : batched over B*H = 64, M=N=1024, K=64
    dim3 gscore(SEQ / 64, SEQ / 128, BATCH * NHEAD);
    gemm_kernel<0, 0><<<gscore, blk>>>(q, k, nullptr, sc,
                                       SEQ, SEQ, HDIM, 0.125f,
                                       (long long)SEQ * HDIM,
                                       (long long)SEQ * HDIM,
                                       (long long)SEQ * SEQ);

    // softmax over last dim: 64*1024 rows
    softmax_kernel<<<BATCH * NHEAD * SEQ, 256>>>(sc);

    // wa = attn @ V : batched, M=1024, N=64, K=1024, scatter to [B,S,D]
    dim3 gav(1, SEQ / 128, BATCH * NHEAD);
    gemm_kernel<1, 2><<<gav, blk>>>(sc, v, nullptr, wa,
                                    SEQ, HDIM, SEQ, 1.f,
                                    (long long)SEQ * SEQ,
                                    (long long)SEQ * HDIM,
                                    0);

    // out = wa @ Wp^T + bp : [4096,1024]
    gemm_kernel<0, 0><<<gproj, blk>>>(wa, Wp, bp, out, NTOK, DIM, DIM, 1.f, 0, 0, 0);
}

// round 3
// speedup vs baseline: 1.9553x; 1.9553x over previous
#include <cuda_runtime.h>
#include <cuda_bf16.h>
#include <cstdint>
#include <math.h>

#define SEQ   1024
#define DIM   1024
#define NHEAD 16
#define HDIM  64
#define BATCH 4
#define NTOK  (BATCH*SEQ)
#define NBH   (BATCH*NHEAD)

// ---------------- scratch (allocation-free rule) ----------------
__device__ __nv_bfloat16 g_xh[NTOK*DIM],  g_xl[NTOK*DIM];          // x split
__device__ __nv_bfloat16 g_wh[4*DIM*DIM], g_wl[4*DIM*DIM];         // Wq,Wk,Wv,Wp split
__device__ __nv_bfloat16 g_qh[NBH*SEQ*HDIM], g_ql[NBH*SEQ*HDIM];   // Q [bh,s,d]
__device__ __nv_bfloat16 g_kh[NBH*SEQ*HDIM], g_kl[NBH*SEQ*HDIM];   // K [bh,s,d]
__device__ __nv_bfloat16 g_vh[NBH*SEQ*HDIM], g_vl[NBH*SEQ*HDIM];   // V [bh,s,d]
__device__ float         g_sc[(long long)NBH*SEQ*SEQ];             // scores fp32
__device__ __nv_bfloat16 g_ah[(long long)NBH*SEQ*SEQ];             // attn hi
__device__ __nv_bfloat16 g_al[(long long)NBH*SEQ*SEQ];             // attn lo
__device__ __nv_bfloat16 g_wah[NTOK*DIM], g_wal[NTOK*DIM];         // wa split

// ---------------- PTX helpers ----------------
__device__ __forceinline__ uint32_t smem_u32(const void* p) {
    uint32_t a;
    asm("{ .reg .u64 t; cvta.to.shared.u64 t, %1; cvt.u32.u64 %0, t; }" : "=r"(a) : "l"(p));
    return a;
}
#define CPA16(d, s)  asm volatile("cp.async.cg.shared.global [%0], [%1], 16;" :: "r"(d), "l"(s) : "memory")
#define CPA_COMMIT() asm volatile("cp.async.commit_group;" ::: "memory")
#define CPA_WAIT(n)  asm volatile("cp.async.wait_group %0;" :: "n"(n) : "memory")

#define LDSM_X4(r, addr) \
    asm volatile("ldmatrix.sync.aligned.m8n8.x4.shared.b16 {%0,%1,%2,%3}, [%4];" \
        : "=r"((r)[0]), "=r"((r)[1]), "=r"((r)[2]), "=r"((r)[3]) : "r"(addr))
#define LDSM_X4T(r, addr) \
    asm volatile("ldmatrix.sync.aligned.m8n8.x4.trans.shared.b16 {%0,%1,%2,%3}, [%4];" \
        : "=r"((r)[0]), "=r"((r)[1]), "=r"((r)[2]), "=r"((r)[3]) : "r"(addr))

#define MMA16816(d, a, b0, b1) \
    asm volatile("mma.sync.aligned.m16n8k16.row.col.f32.bf16.bf16.f32 " \
        "{%0,%1,%2,%3}, {%4,%5,%6,%7}, {%8,%9}, {%0,%1,%2,%3};" \
        : "+f"((d)[0]), "+f"((d)[1]), "+f"((d)[2]), "+f"((d)[3]) \
        : "r"((a)[0]), "r"((a)[1]), "r"((a)[2]), "r"((a)[3]), "r"(b0), "r"(b1))

__device__ __forceinline__ uint32_t sw128(uint32_t boff) {
    return boff ^ ((boff >> 3) & 0x70);
}
__device__ __forceinline__ void split_store(__nv_bfloat16* __restrict__ hi,
                                            __nv_bfloat16* __restrict__ lo,
                                            long long off, float v0, float v1) {
    __nv_bfloat162 H, L;
    H.x = __float2bfloat16(v0); H.y = __float2bfloat16(v1);
    L.x = __float2bfloat16(v0 - __bfloat162float(H.x));
    L.y = __float2bfloat16(v1 - __bfloat162float(H.y));
    *(__nv_bfloat162*)(hi + off) = H;
    *(__nv_bfloat162*)(lo + off) = L;
}

// ---------------------------------------------------------------------------
// mma.sync bf16 GEMM with 3-term split compensation over K' = 3K.
// C[128 x BN] per CTA, 256 threads = 8 warps (4 x 2), warp tile 32 x (BN/2).
// A: [M,K] row-major (hi/lo).   B (BTRANS=0): [N,K] row-major (NT).
//                               B (BTRANS=1): [K,N] row-major (NN, via ldsm.trans).
// Phase 0: Ah*Bh, 1: Al*Bh, 2: Ah*Bl.
// EPI 0: fp32 out  C[z*zsC + m*ldc + n] = alpha*acc (+bias[n])
// EPI 1: split bf16 scatter [B,H,S,Hd] (+bias[n])
// EPI 3: split bf16 scatter wa[B,S,DIM] (z = b*16+h, col = within-head d)
// ---------------------------------------------------------------------------
template<int BN, int BTRANS, int EPI>
__global__ void __launch_bounds__(256, 1)
tc_gemm(const __nv_bfloat16* __restrict__ Ahi, const __nv_bfloat16* __restrict__ Alo,
        const __nv_bfloat16* __restrict__ Bhi, const __nv_bfloat16* __restrict__ Blo,
        const float* __restrict__ bias,
        float* __restrict__ Cf, __nv_bfloat16* __restrict__ Chi, __nv_bfloat16* __restrict__ Clo,
        int K, int lda, int ldb,
        long long zsA, long long zsB, long long zsC, int ldc, float alpha)
{
    extern __shared__ char dsm[];
    constexpr int NTW    = BN / 16;          // n-tiles per warp (8 or 4)
    constexpr int ABYTES = 128 * 128;        // 128 rows x 64 bf16
    constexpr int BBYTES = BN * 128;         // (also = BK*BN*2 when BTRANS, BN=64)
    constexpr int STG    = ABYTES + BBYTES;

    const int tid    = threadIdx.x;
    const int lane   = tid & 31;
    const int wid    = tid >> 5;
    const int warp_m = wid & 3;
    const int warp_n = wid >> 2;
    const int row0   = blockIdx.y * 128;
    const int col0   = blockIdx.x * BN;
    const int z      = blockIdx.z;

    const uint32_t dyn0 = smem_u32(dsm);
    const uint32_t dyn  = (dyn0 + 1023) & ~1023u;

    const __nv_bfloat16* Ah = Ahi + (long long)z * zsA;
    const __nv_bfloat16* Al = Alo + (long long)z * zsA;
    const __nv_bfloat16* Bh = Bhi + (long long)z * zsB;
    const __nv_bfloat16* Bl = Blo + (long long)z * zsB;

    const int nch = 3 * K / 64;

    auto load_chunk = [&](int c) {
        const int st = c & 1;
        const uint32_t abase = dyn + st * STG;
        const uint32_t bbase = abase + ABYTES;
        const int kk   = c * 64;
        const int ph   = kk / K;
        const int koff = kk - ph * K;
        const __nv_bfloat16* As = (ph == 1) ? Al : Ah;
        const __nv_bfloat16* Bs = (ph == 2) ? Bl : Bh;
        #pragma unroll
        for (int i = 0; i < 4; i++) {                    // A: 128 rows x 8 segs
            int lin = tid + i * 256;
            int r = lin >> 3, sg = lin & 7;
            uint32_t boff = (uint32_t)(r * 128 + sg * 16);
            CPA16(abase + sw128(boff),
                  (const void*)(As + (long long)(row0 + r) * lda + koff + sg * 8));
        }
        if (!BTRANS) {                                   // B: BN rows x 8 segs
            #pragma unroll
            for (int i = 0; i < BN / 32; i++) {
                int lin = tid + i * 256;
                int r = lin >> 3, sg = lin & 7;
                uint32_t boff = (uint32_t)(r * 128 + sg * 16);
                CPA16(bbase + sw128(boff),
                      (const void*)(Bs + (long long)(col0 + r) * ldb + koff + sg * 8));
            }
        } else {                                         // B: 64 k-rows x (BN/8) segs
            #pragma unroll
            for (int i = 0; i < BN / 32; i++) {
                int lin = tid + i * 256;
                int r = lin >> 3, sg = lin & 7;
                uint32_t boff = (uint32_t)(r * 128 + sg * 16);
                CPA16(bbase + sw128(boff),
                      (const void*)(Bs + (long long)(koff + r) * ldb + col0 + sg * 8));
            }
        }
        CPA_COMMIT();
    };

    float acc[2][NTW][4];
    #pragma unroll
    for (int i = 0; i < 2; i++)
        #pragma unroll
        for (int j = 0; j < NTW; j++)
            #pragma unroll
            for (int q = 0; q < 4; q++) acc[i][j][q] = 0.f;

    load_chunk(0);

    for (int c = 0; c < nch; c++) {
        if (c + 1 < nch) { load_chunk(c + 1); CPA_WAIT(1); }
        else             { CPA_WAIT(0); }
        __syncthreads();

        const uint32_t ab = dyn + (c & 1) * STG;
        const uint32_t bb = ab + ABYTES;

        #pragma unroll
        for (int ks = 0; ks < 4; ks++) {
            const int kk = ks * 16;
            uint32_t afr[2][4];
            #pragma unroll
            for (int im = 0; im < 2; im++) {
                int r = warp_m * 32 + im * 16 + (lane & 15);
                uint32_t boff = (uint32_t)(r * 128 + kk * 2 + (lane >> 4) * 16);
                LDSM_X4(afr[im], ab + sw128(boff));
            }
            #pragma unroll
            for (int ip = 0; ip < NTW / 2; ip++) {
                uint32_t bfr[4];
                const int q = lane >> 3, rr = lane & 7;
                if (!BTRANS) {
                    int nr = warp_n * (BN / 2) + ip * 16 + ((q >> 1) << 3) + rr;
                    uint32_t boff = (uint32_t)(nr * 128 + (kk + (q & 1) * 8) * 2);
                    LDSM_X4(bfr, bb + sw128(boff));
                } else {
                    int kr = kk + (q & 1) * 8 + rr;
                    int nc = warp_n * (BN / 2) + ip * 16 + ((q >> 1) << 3);
                    uint32_t boff = (uint32_t)(kr * (BN * 2) + nc * 2);
                    LDSM_X4T(bfr, bb + sw128(boff));
                }
                MMA16816(acc[0][2 * ip],     afr[0], bfr[0], bfr[1]);
                MMA16816(acc[0][2 * ip + 1], afr[0], bfr[2], bfr[3]);
                MMA16816(acc[1][2 * ip],     afr[1], bfr[0], bfr[1]);
                MMA16816(acc[1][2 * ip + 1], afr[1], bfr[2], bfr[3]);
            }
        }
        __syncthreads();
    }

    // ---- epilogue ----
    const int g = lane >> 2, t = lane & 3;
    #pragma unroll
    for (int im = 0; im < 2; im++) {
        #pragma unroll
        for (int in = 0; in < NTW; in++) {
            const float* ac = acc[im][in];
            const int n0 = col0 + warp_n * (BN / 2) + in * 8 + t * 2;
            #pragma unroll
            for (int half = 0; half < 2; half++) {
                const int m = row0 + warp_m * 32 + im * 16 + g + half * 8;
                float v0 = ac[half * 2]     * alpha;
                float v1 = ac[half * 2 + 1] * alpha;
                if ((EPI == 0 || EPI == 1) && bias) { v0 += bias[n0]; v1 += bias[n0 + 1]; }
                if (EPI == 0) {
                    *(float2*)(Cf + (long long)z * zsC + (long long)m * ldc + n0) =
                        make_float2(v0, v1);
                } else if (EPI == 1) {
                    int b = m >> 10, s = m & 1023, h = n0 >> 6, d = n0 & 63;
                    long long off = ((((long long)(b * NHEAD + h) << 10) + s) * HDIM) + d;
                    split_store(Chi, Clo, off, v0, v1);
                } else { // EPI == 3
                    int b = z >> 4, h = z & 15;
                    long long off = (((long long)(b << 10) + m) << 10) + h * HDIM + n0;
                    split_store(Chi, Clo, off, v0, v1);
                }
            }
        }
    }
}

// ---------------------------------------------------------------------------
__global__ void __launch_bounds__(256)
split_kernel(const float* __restrict__ in, __nv_bfloat16* __restrict__ hi,
             __nv_bfloat16* __restrict__ lo, int n4)
{
    int i = blockIdx.x * 256 + threadIdx.x;
    if (i >= n4) return;
    float4 v = ((const float4*)in)[i];
    __nv_bfloat16 h0 = __float2bfloat16(v.x), h1 = __float2bfloat16(v.y);
    __nv_bfloat16 h2 = __float2bfloat16(v.z), h3 = __float2bfloat16(v.w);
    __nv_bfloat162 H0; H0.x = h0; H0.y = h1;
    __nv_bfloat162 H1; H1.x = h2; H1.y = h3;
    __nv_bfloat162 L0, L1;
    L0.x = __float2bfloat16(v.x - __bfloat162float(h0));
    L0.y = __float2bfloat16(v.y - __bfloat162float(h1));
    L1.x = __float2bfloat16(v.z - __bfloat162float(h2));
    L1.y = __float2bfloat16(v.w - __bfloat162float(h3));
    ((__nv_bfloat162*)hi)[2 * i]     = H0;
    ((__nv_bfloat162*)hi)[2 * i + 1] = H1;
    ((__nv_bfloat162*)lo)[2 * i]     = L0;
    ((__nv_bfloat162*)lo)[2 * i + 1] = L1;
}

// ---------------------------------------------------------------------------
__global__ void __launch_bounds__(256)
softmax_split(const float* __restrict__ sc, __nv_bfloat16* __restrict__ ah,
              __nv_bfloat16* __restrict__ al)
{
    __shared__ float red[256];
    long long row = blockIdx.x;
    const float4* p = (const float4*)(sc + row * SEQ);
    int tid = threadIdx.x;

    float4 x = p[tid];
    float m = fmaxf(fmaxf(x.x, x.y), fmaxf(x.z, x.w));
    red[tid] = m; __syncthreads();
    #pragma unroll
    for (int s = 128; s > 0; s >>= 1) {
        if (tid < s) red[tid] = fmaxf(red[tid], red[tid + s]);
        __syncthreads();
    }
    float rowmax = red[0];
    __syncthreads();

    x.x = expf(x.x - rowmax);
    x.y = expf(x.y - rowmax);
    x.z = expf(x.z - rowmax);
    x.w = expf(x.w - rowmax);
    red[tid] = x.x + x.y + x.z + x.w; __syncthreads();
    #pragma unroll
    for (int s = 128; s > 0; s >>= 1) {
        if (tid < s) red[tid] += red[tid + s];
        __syncthreads();
    }
    float inv = 1.f / red[0];
    x.x *= inv; x.y *= inv; x.z *= inv; x.w *= inv;

    __nv_bfloat16 h0 = __float2bfloat16(x.x), h1 = __float2bfloat16(x.y);
    __nv_bfloat16 h2 = __float2bfloat16(x.z), h3 = __float2bfloat16(x.w);
    __nv_bfloat162 H0; H0.x = h0; H0.y = h1;
    __nv_bfloat162 H1; H1.x = h2; H1.y = h3;
    __nv_bfloat162 L0, L1;
    L0.x = __float2bfloat16(x.x - __bfloat162float(h0));
    L0.y = __float2bfloat16(x.y - __bfloat162float(h1));
    L1.x = __float2bfloat16(x.z - __bfloat162float(h2));
    L1.y = __float2bfloat16(x.w - __bfloat162float(h3));
    __nv_bfloat162* oh = (__nv_bfloat162*)(ah + row * SEQ);
    __nv_bfloat162* ol = (__nv_bfloat162*)(al + row * SEQ);
    oh[2 * tid] = H0; oh[2 * tid + 1] = H1;
    ol[2 * tid] = L0; ol[2 * tid + 1] = L1;
}

// ---------------------------------------------------------------------------
extern "C" void kernel_launch(void* const* d_in, const int* in_sizes, int n_in,
                              void* d_out, int out_size)
{
    (void)in_sizes; (void)n_in; (void)out_size;
    const float* x  = (const float*)d_in[0];
    const float* Wq = (const float*)d_in[1];
    const float* bq = (const float*)d_in[2];
    const float* Wk = (const float*)d_in[3];
    const float* bk = (const float*)d_in[4];
    const float* Wv = (const float*)d_in[5];
    const float* bv = (const float*)d_in[6];
    const float* Wp = (const float*)d_in[7];
    const float* bp = (const float*)d_in[8];
    float* out = (float*)d_out;

    __nv_bfloat16 *xh, *xl, *wh, *wl, *qh, *ql, *kh, *kl, *vh, *vl, *ah, *al, *wah, *wal;
    float* sc;
    cudaGetSymbolAddress((void**)&xh,  g_xh);
    cudaGetSymbolAddress((void**)&xl,  g_xl);
    cudaGetSymbolAddress((void**)&wh,  g_wh);
    cudaGetSymbolAddress((void**)&wl,  g_wl);
    cudaGetSymbolAddress((void**)&qh,  g_qh);
    cudaGetSymbolAddress((void**)&ql,  g_ql);
    cudaGetSymbolAddress((void**)&kh,  g_kh);
    cudaGetSymbolAddress((void**)&kl,  g_kl);
    cudaGetSymbolAddress((void**)&vh,  g_vh);
    cudaGetSymbolAddress((void**)&vl,  g_vl);
    cudaGetSymbolAddress((void**)&sc,  g_sc);
    cudaGetSymbolAddress((void**)&ah,  g_ah);
    cudaGetSymbolAddress((void**)&al,  g_al);
    cudaGetSymbolAddress((void**)&wah, g_wah);
    cudaGetSymbolAddress((void**)&wal, g_wal);

    const int SM128 = 2 * (16384 + 16384) + 1024;  // 66560
    const int SM64  = 2 * (16384 + 8192)  + 1024;  // 50176
    cudaFuncSetAttribute(tc_gemm<128, 0, 1>, cudaFuncAttributeMaxDynamicSharedMemorySize, SM128);
    cudaFuncSetAttribute(tc_gemm<128, 0, 0>, cudaFuncAttributeMaxDynamicSharedMemorySize, SM128);
    cudaFuncSetAttribute(tc_gemm<64, 1, 3>,  cudaFuncAttributeMaxDynamicSharedMemorySize, SM64);

    // 1. fp32 -> hi/lo bf16 splits
    split_kernel<<<(NTOK * DIM / 4) / 256, 256>>>(x, xh, xl, NTOK * DIM / 4);
    split_kernel<<<(DIM * DIM / 4) / 256, 256>>>(Wq, wh + 0 * DIM * DIM, wl + 0 * DIM * DIM, DIM * DIM / 4);
    split_kernel<<<(DIM * DIM / 4) / 256, 256>>>(Wk, wh + 1 * DIM * DIM, wl + 1 * DIM * DIM, DIM * DIM / 4);
    split_kernel<<<(DIM * DIM / 4) / 256, 256>>>(Wv, wh + 2 * DIM * DIM, wl + 2 * DIM * DIM, DIM * DIM / 4);
    split_kernel<<<(DIM * DIM / 4) / 256, 256>>>(Wp, wh + 3 * DIM * DIM, wl + 3 * DIM * DIM, DIM * DIM / 4);

    dim3 blk(256);

    // 2. projections: M=4096, N=1024, K=1024 -> [B,H,S,Hd] split
    dim3 gp(DIM / 128, NTOK / 128, 1);
    tc_gemm<128, 0, 1><<<gp, blk, SM128>>>(xh, xl, wh + 0 * DIM * DIM, wl + 0 * DIM * DIM, bq,
                                           nullptr, qh, ql, DIM, DIM, DIM, 0, 0, 0, 0, 1.f);
    tc_gemm<128, 0, 1><<<gp, blk, SM128>>>(xh, xl, wh + 1 * DIM * DIM, wl + 1 * DIM * DIM, bk,
                                           nullptr, kh, kl, DIM, DIM, DIM, 0, 0, 0, 0, 1.f);
    tc_gemm<128, 0, 1><<<gp, blk, SM128>>>(xh, xl, wh + 2 * DIM * DIM, wl + 2 * DIM * DIM, bv,
                                           nullptr, vh, vl, DIM, DIM, DIM, 0, 0, 0, 0, 1.f);

    // 3. scores = Q K^T / 8 : batched 64 heads, M=N=1024, K=64 -> fp32
    dim3 gs(SEQ / 128, SEQ / 128, NBH);
    tc_gemm<128, 0, 0><<<gs, blk, SM128>>>(qh, ql, kh, kl, nullptr,
                                           sc, nullptr, nullptr, HDIM, HDIM, HDIM,
                                           (long long)SEQ * HDIM, (long long)SEQ * HDIM,
                                           (long long)SEQ * SEQ, SEQ, 0.125f);

    // 4. softmax + split
    softmax_split<<<NBH * SEQ, 256>>>(sc, ah, al);

    // 5. wa = attn @ V : M=1024, N=64 (NN via ldsm.trans), K=1024 per head
    dim3 ga(1, SEQ / 128, NBH);
    tc_gemm<64, 1, 3><<<ga, blk, SM64>>>(ah, al, vh, vl, nullptr,
                                         nullptr, wah, wal, SEQ, SEQ, HDIM,
                                         (long long)SEQ * SEQ, (long long)SEQ * HDIM,
                                         0, 0, 1.f);

    // 6. out = wa @ Wp^T + bp : fp32 out
    tc_gemm<128, 0, 0><<<gp, blk, SM128>>>(wah, wal, wh + 3 * DIM * DIM, wl + 3 * DIM * DIM, bp,
                                           out, nullptr, nullptr, DIM, DIM, DIM, 0, 0, 0, DIM, 1.f);
}

// round 4
// speedup vs baseline: 2.7415x; 1.4021x over previous
#include <cuda_runtime.h>
#include <cuda_bf16.h>
#include <cstdint>
#include <math.h>

#define SEQ   1024
#define DIM   1024
#define NHEAD 16
#define HDIM  64
#define BATCH 4
#define NTOK  (BATCH*SEQ)
#define NBH   (BATCH*NHEAD)

// ---------------- scratch (allocation-free rule) ----------------
__device__ __nv_bfloat16 g_xh[NTOK*DIM],  g_xl[NTOK*DIM];
__device__ __nv_bfloat16 g_wh[4*DIM*DIM], g_wl[4*DIM*DIM];
__device__ __nv_bfloat16 g_qh[NBH*SEQ*HDIM], g_ql[NBH*SEQ*HDIM];
__device__ __nv_bfloat16 g_kh[NBH*SEQ*HDIM], g_kl[NBH*SEQ*HDIM];
__device__ __nv_bfloat16 g_vh[NBH*SEQ*HDIM], g_vl[NBH*SEQ*HDIM];
__device__ __nv_bfloat16 g_wah[NTOK*DIM], g_wal[NTOK*DIM];

// ---------------- PTX helpers ----------------
__device__ __forceinline__ uint32_t smem_u32(const void* p) {
    uint32_t a;
    asm("{ .reg .u64 t; cvta.to.shared.u64 t, %1; cvt.u32.u64 %0, t; }" : "=r"(a) : "l"(p));
    return a;
}
#define CPA16(d, s)  asm volatile("cp.async.cg.shared.global [%0], [%1], 16;" :: "r"(d), "l"(s) : "memory")
#define CPA_COMMIT() asm volatile("cp.async.commit_group;" ::: "memory")
#define CPA_WAIT(n)  asm volatile("cp.async.wait_group %0;" :: "n"(n) : "memory")

#define LDSM_X4(r, addr) \
    asm volatile("ldmatrix.sync.aligned.m8n8.x4.shared.b16 {%0,%1,%2,%3}, [%4];" \
        : "=r"((r)[0]), "=r"((r)[1]), "=r"((r)[2]), "=r"((r)[3]) : "r"(addr))
#define LDSM_X4T(r, addr) \
    asm volatile("ldmatrix.sync.aligned.m8n8.x4.trans.shared.b16 {%0,%1,%2,%3}, [%4];" \
        : "=r"((r)[0]), "=r"((r)[1]), "=r"((r)[2]), "=r"((r)[3]) : "r"(addr))

#define MMA16816(d, a, b0, b1) \
    asm volatile("mma.sync.aligned.m16n8k16.row.col.f32.bf16.bf16.f32 " \
        "{%0,%1,%2,%3}, {%4,%5,%6,%7}, {%8,%9}, {%0,%1,%2,%3};" \
        : "+f"((d)[0]), "+f"((d)[1]), "+f"((d)[2]), "+f"((d)[3]) \
        : "r"((a)[0]), "r"((a)[1]), "r"((a)[2]), "r"((a)[3]), "r"(b0), "r"(b1))

__device__ __forceinline__ uint32_t sw128(uint32_t boff) {
    return boff ^ ((boff >> 3) & 0x70);
}
__device__ __forceinline__ void split_store(__nv_bfloat16* __restrict__ hi,
                                            __nv_bfloat16* __restrict__ lo,
                                            long long off, float v0, float v1) {
    __nv_bfloat162 H, L;
    H.x = __float2bfloat16(v0); H.y = __float2bfloat16(v1);
    L.x = __float2bfloat16(v0 - __bfloat162float(H.x));
    L.y = __float2bfloat16(v1 - __bfloat162float(H.y));
    *(__nv_bfloat162*)(hi + off) = H;
    *(__nv_bfloat162*)(lo + off) = L;
}
__device__ __forceinline__ void pack_split(float a, float b, uint32_t& h, uint32_t& l) {
    __nv_bfloat162 H, L;
    H.x = __float2bfloat16(a); H.y = __float2bfloat16(b);
    L.x = __float2bfloat16(a - __bfloat162float(H.x));
    L.y = __float2bfloat16(b - __bfloat162float(H.y));
    h = *(uint32_t*)&H; l = *(uint32_t*)&L;
}

// ---------------------------------------------------------------------------
// mma.sync bf16 GEMM with 3-term split compensation over K' = 3K.
// (unchanged working R3 kernel, NT only)
// EPI 0: fp32 out; EPI 1: split bf16 scatter [B,H,S,Hd]
// ---------------------------------------------------------------------------
template<int BN, int EPI>
__global__ void __launch_bounds__(256, 1)
tc_gemm(const __nv_bfloat16* __restrict__ Ahi, const __nv_bfloat16* __restrict__ Alo,
        const __nv_bfloat16* __restrict__ Bhi, const __nv_bfloat16* __restrict__ Blo,
        const float* __restrict__ bias,
        float* __restrict__ Cf, __nv_bfloat16* __restrict__ Chi, __nv_bfloat16* __restrict__ Clo,
        int K, int lda, int ldb, int ldc, float alpha)
{
    extern __shared__ char dsm[];
    constexpr int NTW    = BN / 16;
    constexpr int ABYTES = 128 * 128;
    constexpr int BBYTES = BN * 128;
    constexpr int STG    = ABYTES + BBYTES;

    const int tid    = threadIdx.x;
    const int lane   = tid & 31;
    const int wid    = tid >> 5;
    const int warp_m = wid & 3;
    const int warp_n = wid >> 2;
    const int row0   = blockIdx.y * 128;
    const int col0   = blockIdx.x * BN;

    const uint32_t dyn0 = smem_u32(dsm);
    const uint32_t dyn  = (dyn0 + 1023) & ~1023u;

    const int nch = 3 * K / 64;

    auto load_chunk = [&](int c) {
        const int st = c & 1;
        const uint32_t abase = dyn + st * STG;
        const uint32_t bbase = abase + ABYTES;
        const int kk   = c * 64;
        const int ph   = kk / K;
        const int koff = kk - ph * K;
        const __nv_bfloat16* As = (ph == 1) ? Alo : Ahi;
        const __nv_bfloat16* Bs = (ph == 2) ? Blo : Bhi;
        #pragma unroll
        for (int i = 0; i < 4; i++) {
            int lin = tid + i * 256;
            int r = lin >> 3, sg = lin & 7;
            uint32_t boff = (uint32_t)(r * 128 + sg * 16);
            CPA16(abase + sw128(boff),
                  (const void*)(As + (long long)(row0 + r) * lda + koff + sg * 8));
        }
        #pragma unroll
        for (int i = 0; i < BN / 32; i++) {
            int lin = tid + i * 256;
            int r = lin >> 3, sg = lin & 7;
            uint32_t boff = (uint32_t)(r * 128 + sg * 16);
            CPA16(bbase + sw128(boff),
                  (const void*)(Bs + (long long)(col0 + r) * ldb + koff + sg * 8));
        }
        CPA_COMMIT();
    };

    float acc[2][NTW][4];
    #pragma unroll
    for (int i = 0; i < 2; i++)
        #pragma unroll
        for (int j = 0; j < NTW; j++)
            #pragma unroll
            for (int q = 0; q < 4; q++) acc[i][j][q] = 0.f;

    load_chunk(0);

    for (int c = 0; c < nch; c++) {
        if (c + 1 < nch) { load_chunk(c + 1); CPA_WAIT(1); }
        else             { CPA_WAIT(0); }
        __syncthreads();

        const uint32_t ab = dyn + (c & 1) * STG;
        const uint32_t bb = ab + ABYTES;

        #pragma unroll
        for (int ks = 0; ks < 4; ks++) {
            const int kk = ks * 16;
            uint32_t afr[2][4];
            #pragma unroll
            for (int im = 0; im < 2; im++) {
                int r = warp_m * 32 + im * 16 + (lane & 15);
                uint32_t boff = (uint32_t)(r * 128 + kk * 2 + (lane >> 4) * 16);
                LDSM_X4(afr[im], ab + sw128(boff));
            }
            #pragma unroll
            for (int ip = 0; ip < NTW / 2; ip++) {
                uint32_t bfr[4];
                const int q = lane >> 3, rr = lane & 7;
                int nr = warp_n * (BN / 2) + ip * 16 + ((q >> 1) << 3) + rr;
                uint32_t boff = (uint32_t)(nr * 128 + (kk + (q & 1) * 8) * 2);
                LDSM_X4(bfr, bb + sw128(boff));
                MMA16816(acc[0][2 * ip],     afr[0], bfr[0], bfr[1]);
                MMA16816(acc[0][2 * ip + 1], afr[0], bfr[2], bfr[3]);
                MMA16816(acc[1][2 * ip],     afr[1], bfr[0], bfr[1]);
                MMA16816(acc[1][2 * ip + 1], afr[1], bfr[2], bfr[3]);
            }
        }
        __syncthreads();
    }

    const int g = lane >> 2, t = lane & 3;
    #pragma unroll
    for (int im = 0; im < 2; im++) {
        #pragma unroll
        for (int in = 0; in < NTW; in++) {
            const float* ac = acc[im][in];
            const int n0 = col0 + warp_n * (BN / 2) + in * 8 + t * 2;
            #pragma unroll
            for (int half = 0; half < 2; half++) {
                const int m = row0 + warp_m * 32 + im * 16 + g + half * 8;
                float v0 = ac[half * 2]     * alpha;
                float v1 = ac[half * 2 + 1] * alpha;
                if (bias) { v0 += bias[n0]; v1 += bias[n0 + 1]; }
                if (EPI == 0) {
                    *(float2*)(Cf + (long long)m * ldc + n0) = make_float2(v0, v1);
                } else {
                    int b = m >> 10, s = m & 1023, h = n0 >> 6, d = n0 & 63;
                    long long off = ((((long long)(b * NHEAD + h) << 10) + s) * HDIM) + d;
                    split_store(Chi, Clo, off, v0, v1);
                }
            }
        }
    }
}

// ---------------------------------------------------------------------------
// Fused flash attention: per CTA = (head z, 128 q rows), 256 thr = 8 warps,
// each warp 16 q rows x 64 d.  KV tiles of 64, double buffered.
// S = split-compensated QK^T * 0.125, online softmax in fp32 regs,
// P re-split to bf16 hi/lo in regs, 3-term PV.  Out: wa split [B,S,DIM].
// ---------------------------------------------------------------------------
__global__ void __launch_bounds__(256, 1)
flash_attn(const __nv_bfloat16* __restrict__ qh, const __nv_bfloat16* __restrict__ ql,
           const __nv_bfloat16* __restrict__ kh, const __nv_bfloat16* __restrict__ kl,
           const __nv_bfloat16* __restrict__ vh, const __nv_bfloat16* __restrict__ vl,
           __nv_bfloat16* __restrict__ wah, __nv_bfloat16* __restrict__ wal)
{
    extern __shared__ char dsm[];
    const int tid  = threadIdx.x;
    const int lane = tid & 31;
    const int wid  = tid >> 5;
    const int z    = blockIdx.x;            // b*16 + h
    const int qrow0 = blockIdx.y * 128;

    const uint32_t dyn0 = smem_u32(dsm);
    const uint32_t dyn  = (dyn0 + 1023) & ~1023u;
    const uint32_t sQh = dyn, sQl = dyn + 16384;
    const uint32_t kvb = dyn + 32768;        // + st*32768 : Kh,Kl,Vh,Vl (8KB each)

    const long long zoff = (long long)z * SEQ * HDIM;
    const __nv_bfloat16* Qh = qh + zoff;
    const __nv_bfloat16* Ql = ql + zoff;
    const __nv_bfloat16* Kh = kh + zoff;
    const __nv_bfloat16* Kl = kl + zoff;
    const __nv_bfloat16* Vh = vh + zoff;
    const __nv_bfloat16* Vl = vl + zoff;

    // load Q tile (128 x 64, hi+lo)
    #pragma unroll
    for (int i = 0; i < 4; i++) {
        int lin = tid + i * 256;
        int r = lin >> 3, sg = lin & 7;
        uint32_t sw = sw128((uint32_t)(r * 128 + sg * 16));
        CPA16(sQh + sw, (const void*)(Qh + (long long)(qrow0 + r) * HDIM + sg * 8));
        CPA16(sQl + sw, (const void*)(Ql + (long long)(qrow0 + r) * HDIM + sg * 8));
    }
    CPA_COMMIT();

    auto load_kv = [&](int c) {
        uint32_t b = kvb + (c & 1) * 32768;
        int kv0 = c * 64;
        #pragma unroll
        for (int i = 0; i < 2; i++) {
            int lin = tid + i * 256;
            int r = lin >> 3, sg = lin & 7;
            uint32_t sw = sw128((uint32_t)(r * 128 + sg * 16));
            long long go = (long long)(kv0 + r) * HDIM + sg * 8;
            CPA16(b +         sw, (const void*)(Kh + go));
            CPA16(b + 8192  + sw, (const void*)(Kl + go));
            CPA16(b + 16384 + sw, (const void*)(Vh + go));
            CPA16(b + 24576 + sw, (const void*)(Vl + go));
        }
        CPA_COMMIT();
    };
    load_kv(0);

    const int g = lane >> 2, t = lane & 3;
    float O[8][4];
    #pragma unroll
    for (int j = 0; j < 8; j++)
        #pragma unroll
        for (int q = 0; q < 4; q++) O[j][q] = 0.f;
    float m0 = -1e30f, m1 = -1e30f, l0 = 0.f, l1 = 0.f;

    const int NKV = SEQ / 64;
    for (int c = 0; c < NKV; c++) {
        if (c + 1 < NKV) { load_kv(c + 1); CPA_WAIT(1); }
        else             { CPA_WAIT(0); }
        __syncthreads();

        const uint32_t base = kvb + (c & 1) * 32768;
        const uint32_t bKh = base, bKl = base + 8192;
        const uint32_t bVh = base + 16384, bVl = base + 24576;

        // ---- S = QK^T (3-term split) ----
        float S[8][4];
        #pragma unroll
        for (int j = 0; j < 8; j++)
            #pragma unroll
            for (int q = 0; q < 4; q++) S[j][q] = 0.f;

        #pragma unroll
        for (int ks = 0; ks < 4; ks++) {
            uint32_t aH[4], aL[4];
            {
                int r = wid * 16 + (lane & 15);
                uint32_t boff = (uint32_t)(r * 128 + ks * 32 + (lane >> 4) * 16);
                LDSM_X4(aH, sQh + sw128(boff));
                LDSM_X4(aL, sQl + sw128(boff));
            }
            #pragma unroll
            for (int grp = 0; grp < 4; grp++) {
                uint32_t bH[4], bL[4];
                const int q = lane >> 3, rr = lane & 7;
                int nr = grp * 16 + ((q >> 1) << 3) + rr;
                uint32_t boff = (uint32_t)(nr * 128 + (ks * 16 + (q & 1) * 8) * 2);
                LDSM_X4(bH, bKh + sw128(boff));
                LDSM_X4(bL, bKl + sw128(boff));
                MMA16816(S[2 * grp],     aH, bH[0], bH[1]);
                MMA16816(S[2 * grp + 1], aH, bH[2], bH[3]);
                MMA16816(S[2 * grp],     aL, bH[0], bH[1]);
                MMA16816(S[2 * grp + 1], aL, bH[2], bH[3]);
                MMA16816(S[2 * grp],     aH, bL[0], bL[1]);
                MMA16816(S[2 * grp + 1], aH, bL[2], bL[3]);
            }
        }

        // ---- online softmax ----
        float mx0 = -1e30f, mx1 = -1e30f;
        #pragma unroll
        for (int j = 0; j < 8; j++) {
            S[j][0] *= 0.125f; S[j][1] *= 0.125f; S[j][2] *= 0.125f; S[j][3] *= 0.125f;
            mx0 = fmaxf(mx0, fmaxf(S[j][0], S[j][1]));
            mx1 = fmaxf(mx1, fmaxf(S[j][2], S[j][3]));
        }
        mx0 = fmaxf(mx0, __shfl_xor_sync(0xffffffffu, mx0, 1));
        mx0 = fmaxf(mx0, __shfl_xor_sync(0xffffffffu, mx0, 2));
        mx1 = fmaxf(mx1, __shfl_xor_sync(0xffffffffu, mx1, 1));
        mx1 = fmaxf(mx1, __shfl_xor_sync(0xffffffffu, mx1, 2));
        float nm0 = fmaxf(m0, mx0), nm1 = fmaxf(m1, mx1);
        float c0 = __expf(m0 - nm0), c1 = __expf(m1 - nm1);
        m0 = nm0; m1 = nm1;

        uint32_t PH[4][4], PL[4][4];
        float s0 = 0.f, s1 = 0.f;
        #pragma unroll
        for (int ck = 0; ck < 4; ck++) {
            float p00 = __expf(S[2 * ck][0] - nm0),   p01 = __expf(S[2 * ck][1] - nm0);
            float p02 = __expf(S[2 * ck][2] - nm1),   p03 = __expf(S[2 * ck][3] - nm1);
            float p10 = __expf(S[2 * ck + 1][0] - nm0), p11 = __expf(S[2 * ck + 1][1] - nm0);
            float p12 = __expf(S[2 * ck + 1][2] - nm1), p13 = __expf(S[2 * ck + 1][3] - nm1);
            s0 += p00 + p01 + p10 + p11;
            s1 += p02 + p03 + p12 + p13;
            pack_split(p00, p01, PH[ck][0], PL[ck][0]);
            pack_split(p02, p03, PH[ck][1], PL[ck][1]);
            pack_split(p10, p11, PH[ck][2], PL[ck][2]);
            pack_split(p12, p13, PH[ck][3], PL[ck][3]);
        }
        l0 = l0 * c0 + s0;
        l1 = l1 * c1 + s1;
        #pragma unroll
        for (int j = 0; j < 8; j++) {
            O[j][0] *= c0; O[j][1] *= c0; O[j][2] *= c1; O[j][3] *= c1;
        }

        // ---- O += P V (3-term split) ----
        #pragma unroll
        for (int ck = 0; ck < 4; ck++) {
            #pragma unroll
            for (int dg = 0; dg < 4; dg++) {
                uint32_t bH[4], bL[4];
                const int q = lane >> 3, rr = lane & 7;
                int kr = ck * 16 + (q & 1) * 8 + rr;
                int nc = dg * 16 + ((q >> 1) << 3);
                uint32_t boff = (uint32_t)(kr * 128 + nc * 2);
                LDSM_X4T(bH, bVh + sw128(boff));
                LDSM_X4T(bL, bVl + sw128(boff));
                MMA16816(O[2 * dg],     PH[ck], bH[0], bH[1]);
                MMA16816(O[2 * dg + 1], PH[ck], bH[2], bH[3]);
                MMA16816(O[2 * dg],     PL[ck], bH[0], bH[1]);
                MMA16816(O[2 * dg + 1], PL[ck], bH[2], bH[3]);
                MMA16816(O[2 * dg],     PH[ck], bL[0], bL[1]);
                MMA16816(O[2 * dg + 1], PH[ck], bL[2], bL[3]);
            }
        }
        __syncthreads();
    }

    // ---- finalize + store ----
    l0 += __shfl_xor_sync(0xffffffffu, l0, 1);
    l0 += __shfl_xor_sync(0xffffffffu, l0, 2);
    l1 += __shfl_xor_sync(0xffffffffu, l1, 1);
    l1 += __shfl_xor_sync(0xffffffffu, l1, 2);
    float inv0 = 1.f / l0, inv1 = 1.f / l1;

    const int b = z >> 4, h = z & 15;
    const int r0 = qrow0 + wid * 16 + g;
    #pragma unroll
    for (int j = 0; j < 8; j++) {
        int d = j * 8 + t * 2;
        long long off0 = (((long long)(b << 10) + r0) << 10) + h * HDIM + d;
        long long off1 = (((long long)(b << 10) + r0 + 8) << 10) + h * HDIM + d;
        split_store(wah, wal, off0, O[j][0] * inv0, O[j][1] * inv0);
        split_store(wah, wal, off1, O[j][2] * inv1, O[j][3] * inv1);
    }
}

// ---------------------------------------------------------------------------
__global__ void __launch_bounds__(256)
split_kernel(const float* __restrict__ in, __nv_bfloat16* __restrict__ hi,
             __nv_bfloat16* __restrict__ lo, int n4)
{
    int i = blockIdx.x * 256 + threadIdx.x;
    if (i >= n4) return;
    float4 v = ((const float4*)in)[i];
    __nv_bfloat16 h0 = __float2bfloat16(v.x), h1 = __float2bfloat16(v.y);
    __nv_bfloat16 h2 = __float2bfloat16(v.z), h3 = __float2bfloat16(v.w);
    __nv_bfloat162 H0; H0.x = h0; H0.y = h1;
    __nv_bfloat162 H1; H1.x = h2; H1.y = h3;
    __nv_bfloat162 L0, L1;
    L0.x = __float2bfloat16(v.x - __bfloat162float(h0));
    L0.y = __float2bfloat16(v.y - __bfloat162float(h1));
    L1.x = __float2bfloat16(v.z - __bfloat162float(h2));
    L1.y = __float2bfloat16(v.w - __bfloat162float(h3));
    ((__nv_bfloat162*)hi)[2 * i]     = H0;
    ((__nv_bfloat162*)hi)[2 * i + 1] = H1;
    ((__nv_bfloat162*)lo)[2 * i]     = L0;
    ((__nv_bfloat162*)lo)[2 * i + 1] = L1;
}

// ---------------------------------------------------------------------------
extern "C" void kernel_launch(void* const* d_in, const int* in_sizes, int n_in,
                              void* d_out, int out_size)
{
    (void)in_sizes; (void)n_in; (void)out_size;
    const float* x  = (const float*)d_in[0];
    const float* Wq = (const float*)d_in[1];
    const float* bq = (const float*)d_in[2];
    const float* Wk = (const float*)d_in[3];
    const float* bk = (const float*)d_in[4];
    const float* Wv = (const float*)d_in[5];
    const float* bv = (const float*)d_in[6];
    const float* Wp = (const float*)d_in[7];
    const float* bp = (const float*)d_in[8];
    float* out = (float*)d_out;

    __nv_bfloat16 *xh, *xl, *wh, *wl, *qh, *ql, *kh, *kl, *vh, *vl, *wah, *wal;
    cudaGetSymbolAddress((void**)&xh,  g_xh);
    cudaGetSymbolAddress((void**)&xl,  g_xl);
    cudaGetSymbolAddress((void**)&wh,  g_wh);
    cudaGetSymbolAddress((void**)&wl,  g_wl);
    cudaGetSymbolAddress((void**)&qh,  g_qh);
    cudaGetSymbolAddress((void**)&ql,  g_ql);
    cudaGetSymbolAddress((void**)&kh,  g_kh);
    cudaGetSymbolAddress((void**)&kl,  g_kl);
    cudaGetSymbolAddress((void**)&vh,  g_vh);
    cudaGetSymbolAddress((void**)&vl,  g_vl);
    cudaGetSymbolAddress((void**)&wah, g_wah);
    cudaGetSymbolAddress((void**)&wal, g_wal);

    const int SM128 = 2 * (16384 + 16384) + 1024;
    const int SMFA  = 32768 + 2 * 32768 + 1024;   // 99328
    cudaFuncSetAttribute(tc_gemm<128, 1>, cudaFuncAttributeMaxDynamicSharedMemorySize, SM128);
    cudaFuncSetAttribute(tc_gemm<128, 0>, cudaFuncAttributeMaxDynamicSharedMemorySize, SM128);
    cudaFuncSetAttribute(flash_attn,      cudaFuncAttributeMaxDynamicSharedMemorySize, SMFA);

    // 1. fp32 -> hi/lo bf16 splits
    split_kernel<<<(NTOK * DIM / 4) / 256, 256>>>(x, xh, xl, NTOK * DIM / 4);
    split_kernel<<<(DIM * DIM / 4) / 256, 256>>>(Wq, wh + 0 * DIM * DIM, wl + 0 * DIM * DIM, DIM * DIM / 4);
    split_kernel<<<(DIM * DIM / 4) / 256, 256>>>(Wk, wh + 1 * DIM * DIM, wl + 1 * DIM * DIM, DIM * DIM / 4);
    split_kernel<<<(DIM * DIM / 4) / 256, 256>>>(Wv, wh + 2 * DIM * DIM, wl + 2 * DIM * DIM, DIM * DIM / 4);
    split_kernel<<<(DIM * DIM / 4) / 256, 256>>>(Wp, wh + 3 * DIM * DIM, wl + 3 * DIM * DIM, DIM * DIM / 4);

    dim3 blk(256);

    // 2. projections -> [B,H,S,Hd] hi/lo
    dim3 gp(DIM / 128, NTOK / 128, 1);
    tc_gemm<128, 1><<<gp, blk, SM128>>>(xh, xl, wh + 0 * DIM * DIM, wl + 0 * DIM * DIM, bq,
                                        nullptr, qh, ql, DIM, DIM, DIM, 0, 1.f);
    tc_gemm<128, 1><<<gp, blk, SM128>>>(xh, xl, wh + 1 * DIM * DIM, wl + 1 * DIM * DIM, bk,
                                        nullptr, kh, kl, DIM, DIM, DIM, 0, 1.f);
    tc_gemm<128, 1><<<gp, blk, SM128>>>(xh, xl, wh + 2 * DIM * DIM, wl + 2 * DIM * DIM, bv,
                                        nullptr, vh, vl, DIM, DIM, DIM, 0, 1.f);

    // 3. fused attention -> wa hi/lo [B,S,DIM]
    dim3 gf(NBH, SEQ / 128);
    flash_attn<<<gf, blk, SMFA>>>(qh, ql, kh, kl, vh, vl, wah, wal);

    // 4. out = wa @ Wp^T + bp
    tc_gemm<128, 0><<<gp, blk, SM128>>>(wah, wal, wh + 3 * DIM * DIM, wl + 3 * DIM * DIM, bp,
                                        out, nullptr, nullptr, DIM, DIM, DIM, DIM, 1.f);
}

// round 5
// speedup vs baseline: 3.1780x; 1.1592x over previous
#include <cuda_runtime.h>
#include <cuda_bf16.h>
#include <cstdint>
#include <math.h>

#define SEQ   1024
#define DIM   1024
#define NHEAD 16
#define HDIM  64
#define BATCH 4
#define NTOK  (BATCH*SEQ)
#define NBH   (BATCH*NHEAD)

// ---------------- scratch (allocation-free rule) ----------------
__device__ __nv_bfloat16 g_xh[NTOK*DIM],  g_xl[NTOK*DIM];
__device__ __nv_bfloat16 g_wh[4*DIM*DIM], g_wl[4*DIM*DIM];
__device__ __nv_bfloat16 g_qh[NBH*SEQ*HDIM], g_ql[NBH*SEQ*HDIM];
__device__ __nv_bfloat16 g_kh[NBH*SEQ*HDIM], g_kl[NBH*SEQ*HDIM];
__device__ __nv_bfloat16 g_vh[NBH*SEQ*HDIM], g_vl[NBH*SEQ*HDIM];
__device__ __nv_bfloat16 g_wah[NTOK*DIM], g_wal[NTOK*DIM];

// ---------------- PTX helpers ----------------
__device__ __forceinline__ uint32_t smem_u32(const void* p) {
    uint32_t a;
    asm("{ .reg .u64 t; cvta.to.shared.u64 t, %1; cvt.u32.u64 %0, t; }" : "=r"(a) : "l"(p));
    return a;
}
#define CPA16(d, s)  asm volatile("cp.async.cg.shared.global [%0], [%1], 16;" :: "r"(d), "l"(s) : "memory")
#define CPA_COMMIT() asm volatile("cp.async.commit_group;" ::: "memory")
#define CPA_WAIT(n)  asm volatile("cp.async.wait_group %0;" :: "n"(n) : "memory")

#define LDSM_X4(r, addr) \
    asm volatile("ldmatrix.sync.aligned.m8n8.x4.shared.b16 {%0,%1,%2,%3}, [%4];" \
        : "=r"((r)[0]), "=r"((r)[1]), "=r"((r)[2]), "=r"((r)[3]) : "r"(addr))
#define LDSM_X4T(r, addr) \
    asm volatile("ldmatrix.sync.aligned.m8n8.x4.trans.shared.b16 {%0,%1,%2,%3}, [%4];" \
        : "=r"((r)[0]), "=r"((r)[1]), "=r"((r)[2]), "=r"((r)[3]) : "r"(addr))

#define MMA16816(d, a, b0, b1) \
    asm volatile("mma.sync.aligned.m16n8k16.row.col.f32.bf16.bf16.f32 " \
        "{%0,%1,%2,%3}, {%4,%5,%6,%7}, {%8,%9}, {%0,%1,%2,%3};" \
        : "+f"((d)[0]), "+f"((d)[1]), "+f"((d)[2]), "+f"((d)[3]) \
        : "r"((a)[0]), "r"((a)[1]), "r"((a)[2]), "r"((a)[3]), "r"(b0), "r"(b1))

__device__ __forceinline__ uint32_t sw128(uint32_t boff) {
    return boff ^ ((boff >> 3) & 0x70);
}
__device__ __forceinline__ void split_store(__nv_bfloat16* __restrict__ hi,
                                            __nv_bfloat16* __restrict__ lo,
                                            long long off, float v0, float v1) {
    __nv_bfloat162 H, L;
    H.x = __float2bfloat16(v0); H.y = __float2bfloat16(v1);
    L.x = __float2bfloat16(v0 - __bfloat162float(H.x));
    L.y = __float2bfloat16(v1 - __bfloat162float(H.y));
    *(__nv_bfloat162*)(hi + off) = H;
    *(__nv_bfloat162*)(lo + off) = L;
}
__device__ __forceinline__ void pack_split(float a, float b, uint32_t& h, uint32_t& l) {
    __nv_bfloat162 H, L;
    H.x = __float2bfloat16(a); H.y = __float2bfloat16(b);
    L.x = __float2bfloat16(a - __bfloat162float(H.x));
    L.y = __float2bfloat16(b - __bfloat162float(H.y));
    h = *(uint32_t*)&H; l = *(uint32_t*)&L;
}

struct GParams {
    const __nv_bfloat16* Bh[3];
    const __nv_bfloat16* Bl[3];
    const float*         bias[3];
    __nv_bfloat16*       Ch[3];
    __nv_bfloat16*       Cl[3];
    float*               Cf;
};

// ---------------------------------------------------------------------------
// mma.sync bf16 GEMM, 3-term split compensation computed per K-chunk from
// hi+lo buffers loaded ONCE.  C[128 x BN], 256 thr = 8 warps (4m x 2n).
// 3-stage cp.async pipeline.  blockIdx.z selects weight/bias/output set.
// EPI 0: fp32 out (ldc);  EPI 1: split bf16 scatter [B,H,S,Hd]
// ---------------------------------------------------------------------------
template<int BN, int EPI>
__global__ void __launch_bounds__(256, 1)
tc_gemm(const __nv_bfloat16* __restrict__ Ahi, const __nv_bfloat16* __restrict__ Alo,
        GParams gpar, int K, int lda, int ldb, int ldc)
{
    extern __shared__ char dsm[];
    constexpr int NTW    = BN / 16;
    constexpr int ABYTES = 128 * 128;
    constexpr int BBYTES = BN * 128;
    constexpr int STG    = 2 * ABYTES + 2 * BBYTES;

    const int tid    = threadIdx.x;
    const int lane   = tid & 31;
    const int wid    = tid >> 5;
    const int warp_m = wid & 3;
    const int warp_n = wid >> 2;
    const int row0   = blockIdx.y * 128;
    const int col0   = blockIdx.x * BN;
    const int z      = blockIdx.z;

    const __nv_bfloat16* __restrict__ Bh = gpar.Bh[z];
    const __nv_bfloat16* __restrict__ Bl = gpar.Bl[z];
    const float* __restrict__ bias       = gpar.bias[z];

    const uint32_t dyn0 = smem_u32(dsm);
    const uint32_t dyn  = (dyn0 + 1023) & ~1023u;

    const int nch = K / 64;

    auto load_chunk = [&](int c) {
        const uint32_t s = dyn + (c % 3) * STG;
        const int koff = c * 64;
        #pragma unroll
        for (int i = 0; i < 4; i++) {
            int lin = tid + i * 256;
            int r = lin >> 3, sg = lin & 7;
            uint32_t sw = sw128((uint32_t)(r * 128 + sg * 16));
            long long go = (long long)(row0 + r) * lda + koff + sg * 8;
            CPA16(s + sw,          (const void*)(Ahi + go));
            CPA16(s + ABYTES + sw, (const void*)(Alo + go));
        }
        #pragma unroll
        for (int i = 0; i < BN / 32; i++) {
            int lin = tid + i * 256;
            int r = lin >> 3, sg = lin & 7;
            uint32_t sw = sw128((uint32_t)(r * 128 + sg * 16));
            long long go = (long long)(col0 + r) * ldb + koff + sg * 8;
            CPA16(s + 2 * ABYTES + sw,          (const void*)(Bh + go));
            CPA16(s + 2 * ABYTES + BBYTES + sw, (const void*)(Bl + go));
        }
        CPA_COMMIT();
    };

    float acc[2][NTW][4];
    #pragma unroll
    for (int i = 0; i < 2; i++)
        #pragma unroll
        for (int j = 0; j < NTW; j++)
            #pragma unroll
            for (int q = 0; q < 4; q++) acc[i][j][q] = 0.f;

    load_chunk(0);
    load_chunk(1);

    for (int c = 0; c < nch; c++) {
        if (c + 2 < nch)      { load_chunk(c + 2); CPA_WAIT(2); }
        else if (c + 1 < nch) { CPA_WAIT(1); }
        else                  { CPA_WAIT(0); }
        __syncthreads();

        const uint32_t ah_ = dyn + (c % 3) * STG;
        const uint32_t al_ = ah_ + ABYTES;
        const uint32_t bh_ = ah_ + 2 * ABYTES;
        const uint32_t bl_ = bh_ + BBYTES;

        #pragma unroll
        for (int ks = 0; ks < 4; ks++) {
            uint32_t aH[2][4], aL[2][4];
            #pragma unroll
            for (int im = 0; im < 2; im++) {
                int r = warp_m * 32 + im * 16 + (lane & 15);
                uint32_t boff = (uint32_t)(r * 128 + ks * 32 + (lane >> 4) * 16);
                LDSM_X4(aH[im], ah_ + sw128(boff));
                LDSM_X4(aL[im], al_ + sw128(boff));
            }
            #pragma unroll
            for (int ip = 0; ip < NTW / 2; ip++) {
                uint32_t bH[4], bL[4];
                const int q = lane >> 3, rr = lane & 7;
                int nr = warp_n * (BN / 2) + ip * 16 + ((q >> 1) << 3) + rr;
                uint32_t boff = (uint32_t)(nr * 128 + (ks * 16 + (q & 1) * 8) * 2);
                LDSM_X4(bH, bh_ + sw128(boff));
                LDSM_X4(bL, bl_ + sw128(boff));
                #pragma unroll
                for (int im = 0; im < 2; im++) {
                    MMA16816(acc[im][2 * ip],     aH[im], bH[0], bH[1]);
                    MMA16816(acc[im][2 * ip + 1], aH[im], bH[2], bH[3]);
                    MMA16816(acc[im][2 * ip],     aL[im], bH[0], bH[1]);
                    MMA16816(acc[im][2 * ip + 1], aL[im], bH[2], bH[3]);
                    MMA16816(acc[im][2 * ip],     aH[im], bL[0], bL[1]);
                    MMA16816(acc[im][2 * ip + 1], aH[im], bL[2], bL[3]);
                }
            }
        }
        __syncthreads();
    }

    const int g = lane >> 2, t = lane & 3;
    #pragma unroll
    for (int im = 0; im < 2; im++) {
        #pragma unroll
        for (int in = 0; in < NTW; in++) {
            const float* ac = acc[im][in];
            const int n0 = col0 + warp_n * (BN / 2) + in * 8 + t * 2;
            #pragma unroll
            for (int half = 0; half < 2; half++) {
                const int m = row0 + warp_m * 32 + im * 16 + g + half * 8;
                float v0 = ac[half * 2]     + bias[n0];
                float v1 = ac[half * 2 + 1] + bias[n0 + 1];
                if (EPI == 0) {
                    *(float2*)(gpar.Cf + (long long)m * ldc + n0) = make_float2(v0, v1);
                } else {
                    int b = m >> 10, s = m & 1023, h = n0 >> 6, d = n0 & 63;
                    long long off = ((((long long)(b * NHEAD + h) << 10) + s) * HDIM) + d;
                    split_store(gpar.Ch[z], gpar.Cl[z], off, v0, v1);
                }
            }
        }
    }
}

// ---------------------------------------------------------------------------
// Fused flash attention (as R4) with 3-stage KV pipeline.
// ---------------------------------------------------------------------------
__global__ void __launch_bounds__(256, 1)
flash_attn(const __nv_bfloat16* __restrict__ qh, const __nv_bfloat16* __restrict__ ql,
           const __nv_bfloat16* __restrict__ kh, const __nv_bfloat16* __restrict__ kl,
           const __nv_bfloat16* __restrict__ vh, const __nv_bfloat16* __restrict__ vl,
           __nv_bfloat16* __restrict__ wah, __nv_bfloat16* __restrict__ wal)
{
    extern __shared__ char dsm[];
    const int tid  = threadIdx.x;
    const int lane = tid & 31;
    const int wid  = tid >> 5;
    const int z    = blockIdx.x;
    const int qrow0 = blockIdx.y * 128;

    const uint32_t dyn0 = smem_u32(dsm);
    const uint32_t dyn  = (dyn0 + 1023) & ~1023u;
    const uint32_t sQh = dyn, sQl = dyn + 16384;
    const uint32_t kvb = dyn + 32768;        // + (c%3)*32768 : Kh,Kl,Vh,Vl (8KB each)

    const long long zoff = (long long)z * SEQ * HDIM;
    const __nv_bfloat16* Qh = qh + zoff;
    const __nv_bfloat16* Ql = ql + zoff;
    const __nv_bfloat16* Kh = kh + zoff;
    const __nv_bfloat16* Kl = kl + zoff;
    const __nv_bfloat16* Vh = vh + zoff;
    const __nv_bfloat16* Vl = vl + zoff;

    #pragma unroll
    for (int i = 0; i < 4; i++) {
        int lin = tid + i * 256;
        int r = lin >> 3, sg = lin & 7;
        uint32_t sw = sw128((uint32_t)(r * 128 + sg * 16));
        CPA16(sQh + sw, (const void*)(Qh + (long long)(qrow0 + r) * HDIM + sg * 8));
        CPA16(sQl + sw, (const void*)(Ql + (long long)(qrow0 + r) * HDIM + sg * 8));
    }
    CPA_COMMIT();

    auto load_kv = [&](int c) {
        uint32_t b = kvb + (c % 3) * 32768;
        int kv0 = c * 64;
        #pragma unroll
        for (int i = 0; i < 2; i++) {
            int lin = tid + i * 256;
            int r = lin >> 3, sg = lin & 7;
            uint32_t sw = sw128((uint32_t)(r * 128 + sg * 16));
            long long go = (long long)(kv0 + r) * HDIM + sg * 8;
            CPA16(b +         sw, (const void*)(Kh + go));
            CPA16(b + 8192  + sw, (const void*)(Kl + go));
            CPA16(b + 16384 + sw, (const void*)(Vh + go));
            CPA16(b + 24576 + sw, (const void*)(Vl + go));
        }
        CPA_COMMIT();
    };
    load_kv(0);
    load_kv(1);

    const int g = lane >> 2, t = lane & 3;
    float O[8][4];
    #pragma unroll
    for (int j = 0; j < 8; j++)
        #pragma unroll
        for (int q = 0; q < 4; q++) O[j][q] = 0.f;
    float m0 = -1e30f, m1 = -1e30f, l0 = 0.f, l1 = 0.f;

    const int NKV = SEQ / 64;
    for (int c = 0; c < NKV; c++) {
        if (c + 2 < NKV)      { load_kv(c + 2); CPA_WAIT(2); }
        else if (c + 1 < NKV) { CPA_WAIT(1); }
        else                  { CPA_WAIT(0); }
        __syncthreads();

        const uint32_t base = kvb + (c % 3) * 32768;
        const uint32_t bKh = base, bKl = base + 8192;
        const uint32_t bVh = base + 16384, bVl = base + 24576;

        float S[8][4];
        #pragma unroll
        for (int j = 0; j < 8; j++)
            #pragma unroll
            for (int q = 0; q < 4; q++) S[j][q] = 0.f;

        #pragma unroll
        for (int ks = 0; ks < 4; ks++) {
            uint32_t aH[4], aL[4];
            {
                int r = wid * 16 + (lane & 15);
                uint32_t boff = (uint32_t)(r * 128 + ks * 32 + (lane >> 4) * 16);
                LDSM_X4(aH, sQh + sw128(boff));
                LDSM_X4(aL, sQl + sw128(boff));
            }
            #pragma unroll
            for (int grp = 0; grp < 4; grp++) {
                uint32_t bH[4], bL[4];
                const int q = lane >> 3, rr = lane & 7;
                int nr = grp * 16 + ((q >> 1) << 3) + rr;
                uint32_t boff = (uint32_t)(nr * 128 + (ks * 16 + (q & 1) * 8) * 2);
                LDSM_X4(bH, bKh + sw128(boff));
                LDSM_X4(bL, bKl + sw128(boff));
                MMA16816(S[2 * grp],     aH, bH[0], bH[1]);
                MMA16816(S[2 * grp + 1], aH, bH[2], bH[3]);
                MMA16816(S[2 * grp],     aL, bH[0], bH[1]);
                MMA16816(S[2 * grp + 1], aL, bH[2], bH[3]);
                MMA16816(S[2 * grp],     aH, bL[0], bL[1]);
                MMA16816(S[2 * grp + 1], aH, bL[2], bL[3]);
            }
        }

        float mx0 = -1e30f, mx1 = -1e30f;
        #pragma unroll
        for (int j = 0; j < 8; j++) {
            S[j][0] *= 0.125f; S[j][1] *= 0.125f; S[j][2] *= 0.125f; S[j][3] *= 0.125f;
            mx0 = fmaxf(mx0, fmaxf(S[j][0], S[j][1]));
            mx1 = fmaxf(mx1, fmaxf(S[j][2], S[j][3]));
        }
        mx0 = fmaxf(mx0, __shfl_xor_sync(0xffffffffu, mx0, 1));
        mx0 = fmaxf(mx0, __shfl_xor_sync(0xffffffffu, mx0, 2));
        mx1 = fmaxf(mx1, __shfl_xor_sync(0xffffffffu, mx1, 1));
        mx1 = fmaxf(mx1, __shfl_xor_sync(0xffffffffu, mx1, 2));
        float nm0 = fmaxf(m0, mx0), nm1 = fmaxf(m1, mx1);
        float c0 = __expf(m0 - nm0), c1 = __expf(m1 - nm1);
        m0 = nm0; m1 = nm1;

        uint32_t PH[4][4], PL[4][4];
        float s0 = 0.f, s1 = 0.f;
        #pragma unroll
        for (int ck = 0; ck < 4; ck++) {
            float p00 = __expf(S[2 * ck][0] - nm0),   p01 = __expf(S[2 * ck][1] - nm0);
            float p02 = __expf(S[2 * ck][2] - nm1),   p03 = __expf(S[2 * ck][3] - nm1);
            float p10 = __expf(S[2 * ck + 1][0] - nm0), p11 = __expf(S[2 * ck + 1][1] - nm0);
            float p12 = __expf(S[2 * ck + 1][2] - nm1), p13 = __expf(S[2 * ck + 1][3] - nm1);
            s0 += p00 + p01 + p10 + p11;
            s1 += p02 + p03 + p12 + p13;
            pack_split(p00, p01, PH[ck][0], PL[ck][0]);
            pack_split(p02, p03, PH[ck][1], PL[ck][1]);
            pack_split(p10, p11, PH[ck][2], PL[ck][2]);
            pack_split(p12, p13, PH[ck][3], PL[ck][3]);
        }
        l0 = l0 * c0 + s0;
        l1 = l1 * c1 + s1;
        #pragma unroll
        for (int j = 0; j < 8; j++) {
            O[j][0] *= c0; O[j][1] *= c0; O[j][2] *= c1; O[j][3] *= c1;
        }

        #pragma unroll
        for (int ck = 0; ck < 4; ck++) {
            #pragma unroll
            for (int dg = 0; dg < 4; dg++) {
                uint32_t bH[4], bL[4];
                const int q = lane >> 3, rr = lane & 7;
                int kr = ck * 16 + (q & 1) * 8 + rr;
                int nc = dg * 16 + ((q >> 1) << 3);
                uint32_t boff = (uint32_t)(kr * 128 + nc * 2);
                LDSM_X4T(bH, bVh + sw128(boff));
                LDSM_X4T(bL, bVl + sw128(boff));
                MMA16816(O[2 * dg],     PH[ck], bH[0], bH[1]);
                MMA16816(O[2 * dg + 1], PH[ck], bH[2], bH[3]);
                MMA16816(O[2 * dg],     PL[ck], bH[0], bH[1]);
                MMA16816(O[2 * dg + 1], PL[ck], bH[2], bH[3]);
                MMA16816(O[2 * dg],     PH[ck], bL[0], bL[1]);
                MMA16816(O[2 * dg + 1], PH[ck], bL[2], bL[3]);
            }
        }
        __syncthreads();
    }

    l0 += __shfl_xor_sync(0xffffffffu, l0, 1);
    l0 += __shfl_xor_sync(0xffffffffu, l0, 2);
    l1 += __shfl_xor_sync(0xffffffffu, l1, 1);
    l1 += __shfl_xor_sync(0xffffffffu, l1, 2);
    float inv0 = 1.f / l0, inv1 = 1.f / l1;

    const int b = z >> 4, h = z & 15;
    const int r0 = qrow0 + wid * 16 + g;
    #pragma unroll
    for (int j = 0; j < 8; j++) {
        int d = j * 8 + t * 2;
        long long off0 = (((long long)(b << 10) + r0) << 10) + h * HDIM + d;
        long long off1 = (((long long)(b << 10) + r0 + 8) << 10) + h * HDIM + d;
        split_store(wah, wal, off0, O[j][0] * inv0, O[j][1] * inv0);
        split_store(wah, wal, off1, O[j][2] * inv1, O[j][3] * inv1);
    }
}

// ---------------------------------------------------------------------------
// merged fp32 -> hi/lo bf16 split for x + 4 weight matrices in ONE launch.
// region 0: x (1M float4), regions 1..4: weights (256K float4 each).
// ---------------------------------------------------------------------------
struct SplitP {
    const float* in[5];
    __nv_bfloat16* hi[5];
    __nv_bfloat16* lo[5];
};

__global__ void __launch_bounds__(256)
split_all(SplitP p)
{
    int idx = blockIdx.x * 256 + threadIdx.x;
    int r, local;
    if (idx < (1 << 20)) { r = 0; local = idx; }
    else {
        int t2 = idx - (1 << 20);
        r = 1 + (t2 >> 18);
        local = t2 & ((1 << 18) - 1);
    }
    float4 v = ((const float4*)p.in[r])[local];
    __nv_bfloat16 h0 = __float2bfloat16(v.x), h1 = __float2bfloat16(v.y);
    __nv_bfloat16 h2 = __float2bfloat16(v.z), h3 = __float2bfloat16(v.w);
    __nv_bfloat162 H0; H0.x = h0; H0.y = h1;
    __nv_bfloat162 H1; H1.x = h2; H1.y = h3;
    __nv_bfloat162 L0, L1;
    L0.x = __float2bfloat16(v.x - __bfloat162float(h0));
    L0.y = __float2bfloat16(v.y - __bfloat162float(h1));
    L1.x = __float2bfloat16(v.z - __bfloat162float(h2));
    L1.y = __float2bfloat16(v.w - __bfloat162float(h3));
    ((__nv_bfloat162*)p.hi[r])[2 * local]     = H0;
    ((__nv_bfloat162*)p.hi[r])[2 * local + 1] = H1;
    ((__nv_bfloat162*)p.lo[r])[2 * local]     = L0;
    ((__nv_bfloat162*)p.lo[r])[2 * local + 1] = L1;
}

// ---------------------------------------------------------------------------
extern "C" void kernel_launch(void* const* d_in, const int* in_sizes, int n_in,
                              void* d_out, int out_size)
{
    (void)in_sizes; (void)n_in; (void)out_size;
    const float* x  = (const float*)d_in[0];
    const float* Wq = (const float*)d_in[1];
    const float* bq = (const float*)d_in[2];
    const float* Wk = (const float*)d_in[3];
    const float* bk = (const float*)d_in[4];
    const float* Wv = (const float*)d_in[5];
    const float* bv = (const float*)d_in[6];
    const float* Wp = (const float*)d_in[7];
    const float* bp = (const float*)d_in[8];
    float* out = (float*)d_out;

    __nv_bfloat16 *xh, *xl, *wh, *wl, *qh, *ql, *kh, *kl, *vh, *vl, *wah, *wal;
    cudaGetSymbolAddress((void**)&xh,  g_xh);
    cudaGetSymbolAddress((void**)&xl,  g_xl);
    cudaGetSymbolAddress((void**)&wh,  g_wh);
    cudaGetSymbolAddress((void**)&wl,  g_wl);
    cudaGetSymbolAddress((void**)&qh,  g_qh);
    cudaGetSymbolAddress((void**)&ql,  g_ql);
    cudaGetSymbolAddress((void**)&kh,  g_kh);
    cudaGetSymbolAddress((void**)&kl,  g_kl);
    cudaGetSymbolAddress((void**)&vh,  g_vh);
    cudaGetSymbolAddress((void**)&vl,  g_vl);
    cudaGetSymbolAddress((void**)&wah, g_wah);
    cudaGetSymbolAddress((void**)&wal, g_wal);

    const int SM128 = 3 * 65536 + 1024;           // 197632
    const int SMFA  = 32768 + 3 * 32768 + 1024;   // 132096
    cudaFuncSetAttribute(tc_gemm<128, 1>, cudaFuncAttributeMaxDynamicSharedMemorySize, SM128);
    cudaFuncSetAttribute(tc_gemm<128, 0>, cudaFuncAttributeMaxDynamicSharedMemorySize, SM128);
    cudaFuncSetAttribute(flash_attn,      cudaFuncAttributeMaxDynamicSharedMemorySize, SMFA);

    // 1. merged fp32 -> hi/lo bf16 splits
    SplitP sp;
    sp.in[0] = x;  sp.hi[0] = xh;                  sp.lo[0] = xl;
    sp.in[1] = Wq; sp.hi[1] = wh + 0 * DIM * DIM;  sp.lo[1] = wl + 0 * DIM * DIM;
    sp.in[2] = Wk; sp.hi[2] = wh + 1 * DIM * DIM;  sp.lo[2] = wl + 1 * DIM * DIM;
    sp.in[3] = Wv; sp.hi[3] = wh + 2 * DIM * DIM;  sp.lo[3] = wl + 2 * DIM * DIM;
    sp.in[4] = Wp; sp.hi[4] = wh + 3 * DIM * DIM;  sp.lo[4] = wl + 3 * DIM * DIM;
    split_all<<<(1 << 20) / 256 + 4 * ((1 << 18) / 256), 256>>>(sp);

    dim3 blk(256);

    // 2. fused Q/K/V projections (z selects weight set) -> [B,H,S,Hd] hi/lo
    GParams gq = {};
    gq.Bh[0] = wh + 0 * DIM * DIM; gq.Bl[0] = wl + 0 * DIM * DIM; gq.bias[0] = bq;
    gq.Bh[1] = wh + 1 * DIM * DIM; gq.Bl[1] = wl + 1 * DIM * DIM; gq.bias[1] = bk;
    gq.Bh[2] = wh + 2 * DIM * DIM; gq.Bl[2] = wl + 2 * DIM * DIM; gq.bias[2] = bv;
    gq.Ch[0] = qh; gq.Cl[0] = ql;
    gq.Ch[1] = kh; gq.Cl[1] = kl;
    gq.Ch[2] = vh; gq.Cl[2] = vl;
    dim3 gp(DIM / 128, NTOK / 128, 3);
    tc_gemm<128, 1><<<gp, blk, SM128>>>(xh, xl, gq, DIM, DIM, DIM, 0);

    // 3. fused attention -> wa hi/lo [B,S,DIM]
    dim3 gf(NBH, SEQ / 128);
    flash_attn<<<gf, blk, SMFA>>>(qh, ql, kh, kl, vh, vl, wah, wal);

    // 4. out = wa @ Wp^T + bp
    GParams go = {};
    go.Bh[0] = wh + 3 * DIM * DIM; go.Bl[0] = wl + 3 * DIM * DIM; go.bias[0] = bp;
    go.Cf = out;
    dim3 gop(DIM / 128, NTOK / 128, 1);
    tc_gemm<128, 0><<<gop, blk, SM128>>>(wah, wal, go, DIM, DIM, DIM, DIM);
}